// round 9
// baseline (speedup 1.0000x reference)
#include <cuda_runtime.h>

#define N_NODES 50000
#define N_EDGES 800000
#define IN_CH   64
#define HID     128
#define LAST_HID 256
#define CAP     96          // per-node adjacency capacity; P(Poisson(16) > 96) ~ 1e-40
#define FC1_SPLIT 4

typedef unsigned long long u64;

// ---------------- scratch (static device arrays; no allocation) ----------------
__device__ __align__(16) float g_agg[N_NODES * IN_CH];
__device__ int   g_cnt[N_NODES];                 // degree counters (atomic cursors)
__device__ int   g_slots[N_NODES * CAP];         // bucketed adjacency: src per slot
__device__ float g_s[N_NODES];
__device__ float g_t[N_NODES];
__device__ __align__(16) float g_v[N_NODES];
__device__ float g_z[LAST_HID];
__device__ int   g_is64;

// ---------------- f32x2 helpers ----------------
__device__ __forceinline__ void fma2(u64& acc, u64 a, u64 b) {
    asm("fma.rn.f32x2 %0, %1, %2, %0;" : "+l"(acc) : "l"(a), "l"(b));
}
__device__ __forceinline__ float2 unpack2(u64 v) {
    float2 r; asm("mov.b64 {%0, %1}, %2;" : "=f"(r.x), "=f"(r.y) : "l"(v)); return r;
}

// ---------------- edge accessors ----------------
__device__ __forceinline__ int edge_at(const void* ei, int flat_idx, int is64) {
    if (is64) return (int)reinterpret_cast<const long long*>(ei)[flat_idx];
    return reinterpret_cast<const int*>(ei)[flat_idx];
}

// ---------------- K0: zero counters + seed z + detect dtype ----------------
__global__ void k_init(const int* __restrict__ ei32, const float* __restrict__ fc1b) {
    int i = blockIdx.x * blockDim.x + threadIdx.x;
    int stride = gridDim.x * blockDim.x;
    for (int j = i; j < N_NODES; j += stride) g_cnt[j] = 0;
    if (i < LAST_HID) g_z[i] = fc1b[i];
    if (i == 0) {
        int is64 = 1;
        for (int k = 0; k < 256; k++) {
            int idx = 2 * (k * 3000) + 1;      // odd int32 words, < 1.6M
            if (ei32[idx] != 0) { is64 = 0; break; }
        }
        g_is64 = is64;
    }
}

// ---------------- K1: single-pass bucket fill (adjacency + degree) ----------------
__global__ __launch_bounds__(256) void k_fill(const void* __restrict__ ei) {
    int e = blockIdx.x * blockDim.x + threadIdx.x;
    if (e >= N_EDGES) return;
    int is64 = g_is64;
    int src = edge_at(ei, e, is64);
    int dst = edge_at(ei, N_EDGES + e, is64);
    if ((unsigned)dst >= N_NODES || (unsigned)src >= N_NODES) return;
    int pos = atomicAdd(&g_cnt[dst], 1);
    if (pos < CAP) g_slots[dst * CAP + pos] = src;
}

// ---------------- K2: gather-aggregate x rows (16 threads/node, float4) ----------------
__global__ __launch_bounds__(256) void k_gather1(const float* __restrict__ x) {
    int t = blockIdx.x * blockDim.x + threadIdx.x;
    int node = t >> 4;
    if (node >= N_NODES) return;
    int lane = t & 15;
    int deg = g_cnt[node];
    int n = min(deg, CAP);
    const int* sl = g_slots + node * CAP;
    const float4* xp = reinterpret_cast<const float4*>(x);
    float4 accA = make_float4(0.f, 0.f, 0.f, 0.f);
    float4 accB = make_float4(0.f, 0.f, 0.f, 0.f);
    int e = 0;
    for (; e + 2 <= n; e += 2) {
        int s0 = sl[e];
        int s1 = sl[e + 1];
        float4 a = xp[s0 * 16 + lane];
        float4 b = xp[s1 * 16 + lane];
        accA.x += a.x; accA.y += a.y; accA.z += a.z; accA.w += a.w;
        accB.x += b.x; accB.y += b.y; accB.z += b.z; accB.w += b.w;
    }
    if (e < n) {
        int s0 = sl[e];
        float4 a = xp[s0 * 16 + lane];
        accA.x += a.x; accA.y += a.y; accA.z += a.z; accA.w += a.w;
    }
    accA.x += accB.x; accA.y += accB.y; accA.z += accB.z; accA.w += accB.w;
    reinterpret_cast<float4*>(g_agg)[node * 16 + lane] = accA;
}

// ---------------- K3: register-tiled layer1 GEMM + relu + rank-1 pre-dots ----------------
// Tile: 128 nodes x 128 outputs per block; thread = 4 nodes x 8 outputs.
// A = [agg/deg | x] (K=128), W = [W1l | W1r]; k-chunked (32) through smem.
// Row stride 36 floats (144B): +1 quad-bank rotation/row for conflict-free LDS.128.
#define ROWSTR 36
__global__ __launch_bounds__(512, 1) void k_layer1(const float* __restrict__ x,
                                                   const float* __restrict__ W1l,
                                                   const float* __restrict__ b1,
                                                   const float* __restrict__ W1r,
                                                   const float* __restrict__ W2l,
                                                   const float* __restrict__ W2r) {
    __shared__ __align__(16) float sA[128 * ROWSTR];   // 18 KB
    __shared__ __align__(16) float sW[128 * ROWSTR];   // 18 KB
    __shared__ float sb[HID], s2l[HID], s2r[HID], sInv[128], sS[128], sT[128];

    int tid = threadIdx.x;
    int jgrp = tid & 15;        // output lane group: j = jgrp + 16*jj
    int rgrp = tid >> 4;        // node row group: r = rgrp*4 + i   (rgrp 0..31)
    int nb = blockIdx.x * 128;

    if (tid < 128) {
        int node = nb + tid;
        sInv[tid] = (node < N_NODES) ? 1.0f / fmaxf((float)g_cnt[node], 1.0f) : 0.f;
        sb[tid]  = b1[tid];
        s2l[tid] = W2l[tid];
        s2r[tid] = W2r[tid];
        sS[tid] = 0.f; sT[tid] = 0.f;
    }

    u64 acc[32];                 // [4 r][8 jj], each u64 = k-pair partial sums
#pragma unroll
    for (int q = 0; q < 32; q++) acc[q] = 0ull;

    const float4* agg4 = reinterpret_cast<const float4*>(g_agg);
    const float4* x4   = reinterpret_cast<const float4*>(x);
    const float4* wl4  = reinterpret_cast<const float4*>(W1l);
    const float4* wr4  = reinterpret_cast<const float4*>(W1r);

    for (int c = 0; c < 4; c++) {          // 4 k-chunks of 32
        __syncthreads();
        // stage A chunk (with deg-normalization for agg half) and W chunk
        for (int idx = tid; idx < 1024; idx += 512) {
            int row = idx >> 3, q = idx & 7;
            int node = nb + row;
            float4 av = make_float4(0.f, 0.f, 0.f, 0.f);
            if (node < N_NODES) {
                if (c < 2) {
                    av = agg4[node * 16 + c * 8 + q];
                    float iv = sInv[row];
                    av.x *= iv; av.y *= iv; av.z *= iv; av.w *= iv;
                } else {
                    av = x4[node * 16 + (c - 2) * 8 + q];
                }
            }
            *reinterpret_cast<float4*>(sA + row * ROWSTR + q * 4) = av;
            float4 wv = (c < 2) ? wl4[row * 16 + c * 8 + q]
                                : wr4[row * 16 + (c - 2) * 8 + q];
            *reinterpret_cast<float4*>(sW + row * ROWSTR + q * 4) = wv;
        }
        __syncthreads();

#pragma unroll
        for (int kq = 0; kq < 8; kq++) {   // k-quad = 4 floats = 2 k-pairs
            u64 ar[4][2];
#pragma unroll
            for (int r = 0; r < 4; r++) {
                ulonglong2 av = *reinterpret_cast<const ulonglong2*>(
                    sA + (rgrp * 4 + r) * ROWSTR + kq * 4);
                ar[r][0] = av.x; ar[r][1] = av.y;
            }
#pragma unroll
            for (int half = 0; half < 2; half++) {
                u64 wj[4][2];
#pragma unroll
                for (int j2 = 0; j2 < 4; j2++) {
                    int j = jgrp + 16 * (half * 4 + j2);
                    ulonglong2 wv = *reinterpret_cast<const ulonglong2*>(
                        sW + j * ROWSTR + kq * 4);
                    wj[j2][0] = wv.x; wj[j2][1] = wv.y;
                }
#pragma unroll
                for (int r = 0; r < 4; r++)
#pragma unroll
                    for (int j2 = 0; j2 < 4; j2++) {
                        fma2(acc[r * 8 + half * 4 + j2], ar[r][0], wj[j2][0]);
                        fma2(acc[r * 8 + half * 4 + j2], ar[r][1], wj[j2][1]);
                    }
            }
        }
    }

    // epilogue: h = relu(dot + b); fold into rank-1 scalars s,t
    float sp[4] = {0.f, 0.f, 0.f, 0.f};
    float tp[4] = {0.f, 0.f, 0.f, 0.f};
#pragma unroll
    for (int r = 0; r < 4; r++)
#pragma unroll
        for (int jj = 0; jj < 8; jj++) {
            int j = jgrp + 16 * jj;
            float2 f = unpack2(acc[r * 8 + jj]);
            float h = fmaxf(f.x + f.y + sb[j], 0.f);
            sp[r] = fmaf(h, s2l[j], sp[r]);
            tp[r] = fmaf(h, s2r[j], tp[r]);
        }
#pragma unroll
    for (int r = 0; r < 4; r++) {
        atomicAdd(&sS[rgrp * 4 + r], sp[r]);
        atomicAdd(&sT[rgrp * 4 + r], tp[r]);
    }
    __syncthreads();
    if (tid < 128) {
        int node = nb + tid;
        if (node < N_NODES) {
            g_s[node] = sS[tid];
            g_t[node] = sT[tid];
        }
    }
}

// ---------------- K4: layer-2 gather + v epilogue ----------------
__global__ __launch_bounds__(256) void k_gather2v(const float* __restrict__ b2l) {
    int i = blockIdx.x * blockDim.x + threadIdx.x;
    if (i >= N_NODES) return;
    int deg = g_cnt[i];
    int n = min(deg, CAP);
    const int* sl = g_slots + i * CAP;
    float acc = 0.f;
    for (int e = 0; e < n; e++) acc += g_s[sl[e]];
    float inv = 1.0f / fmaxf((float)deg, 1.0f);
    g_v[i] = fmaxf(fmaf(acc, inv, b2l[0] + g_t[i]), 0.f);
}

// ---------------- K5: z += partial(fc1_W @ v), split-K ----------------
__global__ __launch_bounds__(256) void k_fc1(const float* __restrict__ fc1W) {
    int r     = blockIdx.x & (LAST_HID - 1);
    int split = blockIdx.x >> 8;                     // 0..FC1_SPLIT-1
    const int chunk4 = (N_NODES / 4) / FC1_SPLIT;    // 3125 float4s
    int base = split * chunk4;
    const float4* wp = reinterpret_cast<const float4*>(fc1W + (size_t)r * N_NODES) + base;
    const float4* vp = reinterpret_cast<const float4*>(g_v) + base;
    float acc = 0.f;
    for (int idx = threadIdx.x; idx < chunk4; idx += 256) {
        float4 w = wp[idx];
        float4 v = vp[idx];
        acc = fmaf(w.x, v.x, acc);
        acc = fmaf(w.y, v.y, acc);
        acc = fmaf(w.z, v.z, acc);
        acc = fmaf(w.w, v.w, acc);
    }
    __shared__ float red[256];
    red[threadIdx.x] = acc;
    __syncthreads();
#pragma unroll
    for (int off = 128; off > 0; off >>= 1) {
        if (threadIdx.x < off) red[threadIdx.x] += red[threadIdx.x + off];
        __syncthreads();
    }
    if (threadIdx.x == 0) atomicAdd(&g_z[r], red[0]);
}

// ---------------- K6: pred ----------------
__global__ __launch_bounds__(256) void k_final(const float* __restrict__ fc2W,
                                               const float* __restrict__ fc2b,
                                               float* __restrict__ out) {
    __shared__ float red[256];
    int tid = threadIdx.x;
    red[tid] = fc2W[tid] * g_z[tid];
    __syncthreads();
#pragma unroll
    for (int off = 128; off > 0; off >>= 1) {
        if (tid < off) red[tid] += red[tid + off];
        __syncthreads();
    }
    if (tid == 0) out[0] = red[0] + fc2b[0];
}

// ---------------- launch ----------------
extern "C" void kernel_launch(void* const* d_in, const int* in_sizes, int n_in,
                              void* d_out, int out_size) {
    const float* x    = (const float*)d_in[0];
    const void*  ei   = d_in[1];
    const float* W1l  = (const float*)d_in[2];
    const float* b1l  = (const float*)d_in[3];
    const float* W1r  = (const float*)d_in[4];
    const float* W2l  = (const float*)d_in[5];
    const float* b2l  = (const float*)d_in[6];
    const float* W2r  = (const float*)d_in[7];
    const float* fc1W = (const float*)d_in[8];
    const float* fc1b = (const float*)d_in[9];
    const float* fc2W = (const float*)d_in[10];
    const float* fc2b = (const float*)d_in[11];
    float* out = (float*)d_out;

    k_init<<<256, 256>>>((const int*)ei, fc1b);
    k_fill<<<(N_EDGES + 255) / 256, 256>>>(ei);
    k_gather1<<<(N_NODES * 16 + 255) / 256, 256>>>(x);
    k_layer1<<<(N_NODES + 127) / 128, 512>>>(x, W1l, b1l, W1r, W2l, W2r);
    k_gather2v<<<(N_NODES + 255) / 256, 256>>>(b2l);
    k_fc1<<<LAST_HID * FC1_SPLIT, 256>>>(fc1W);
    k_final<<<1, 256>>>(fc2W, fc2b, out);
}

// round 10
// speedup vs baseline: 1.0078x; 1.0078x over previous
#include <cuda_runtime.h>

#define N_NODES 50000
#define N_EDGES 800000
#define IN_CH   64
#define HID     128
#define LAST_HID 256
#define CAP     96          // per-node adjacency capacity; P(Poisson(16) > 96) ~ 1e-40
#define FC1_SPLIT 4

typedef unsigned long long u64;

// ---------------- scratch (static device arrays; no allocation) ----------------
__device__ __align__(16) float g_agg[N_NODES * IN_CH];
__device__ int   g_cnt[N_NODES];                 // degree counters (atomic cursors)
__device__ int   g_slots[N_NODES * CAP];         // bucketed adjacency: src per slot
__device__ float g_s[N_NODES];
__device__ float g_t[N_NODES];
__device__ __align__(16) float g_v[N_NODES];
__device__ float g_z[LAST_HID];
__device__ int   g_is64;

// ---------------- f32x2 helpers ----------------
__device__ __forceinline__ void fma2(u64& acc, u64 a, u64 b) {
    asm("fma.rn.f32x2 %0, %1, %2, %0;" : "+l"(acc) : "l"(a), "l"(b));
}
__device__ __forceinline__ float2 unpack2(u64 v) {
    float2 r; asm("mov.b64 {%0, %1}, %2;" : "=f"(r.x), "=f"(r.y) : "l"(v)); return r;
}

// ---------------- edge accessors ----------------
__device__ __forceinline__ int edge_at(const void* ei, int flat_idx, int is64) {
    if (is64) return (int)reinterpret_cast<const long long*>(ei)[flat_idx];
    return reinterpret_cast<const int*>(ei)[flat_idx];
}

// ---------------- K0: zero counters + seed z + detect dtype ----------------
__global__ void k_init(const int* __restrict__ ei32, const float* __restrict__ fc1b) {
    int i = blockIdx.x * blockDim.x + threadIdx.x;
    int stride = gridDim.x * blockDim.x;
    for (int j = i; j < N_NODES; j += stride) g_cnt[j] = 0;
    if (i < LAST_HID) g_z[i] = fc1b[i];
    if (i == 0) {
        int is64 = 1;
        for (int k = 0; k < 256; k++) {
            int idx = 2 * (k * 3000) + 1;      // odd int32 words, < 1.6M
            if (ei32[idx] != 0) { is64 = 0; break; }
        }
        g_is64 = is64;
    }
}

// ---------------- K1: single-pass bucket fill (adjacency + degree) ----------------
__global__ __launch_bounds__(256) void k_fill(const void* __restrict__ ei) {
    int e = blockIdx.x * blockDim.x + threadIdx.x;
    if (e >= N_EDGES) return;
    int is64 = g_is64;
    int src = edge_at(ei, e, is64);
    int dst = edge_at(ei, N_EDGES + e, is64);
    if ((unsigned)dst >= N_NODES || (unsigned)src >= N_NODES) return;
    int pos = atomicAdd(&g_cnt[dst], 1);
    if (pos < CAP) g_slots[dst * CAP + pos] = src;
}

// ---------------- K2: gather-aggregate x rows (16 threads/node, float4) ----------------
__global__ __launch_bounds__(256) void k_gather1(const float* __restrict__ x) {
    int t = blockIdx.x * blockDim.x + threadIdx.x;
    int node = t >> 4;
    if (node >= N_NODES) return;
    int lane = t & 15;
    int deg = g_cnt[node];
    int n = min(deg, CAP);
    const int* sl = g_slots + node * CAP;
    const float4* xp = reinterpret_cast<const float4*>(x);
    float4 accA = make_float4(0.f, 0.f, 0.f, 0.f);
    float4 accB = make_float4(0.f, 0.f, 0.f, 0.f);
    int e = 0;
    for (; e + 2 <= n; e += 2) {
        int s0 = sl[e];
        int s1 = sl[e + 1];
        float4 a = xp[s0 * 16 + lane];
        float4 b = xp[s1 * 16 + lane];
        accA.x += a.x; accA.y += a.y; accA.z += a.z; accA.w += a.w;
        accB.x += b.x; accB.y += b.y; accB.z += b.z; accB.w += b.w;
    }
    if (e < n) {
        int s0 = sl[e];
        float4 a = xp[s0 * 16 + lane];
        accA.x += a.x; accA.y += a.y; accA.z += a.z; accA.w += a.w;
    }
    accA.x += accB.x; accA.y += accB.y; accA.z += accB.z; accA.w += accB.w;
    reinterpret_cast<float4*>(g_agg)[node * 16 + lane] = accA;
}

// ---------------- K3: register-tiled layer1 GEMM + relu + rank-1 pre-dots ----------------
// Block tile: 32 nodes x 128 outputs; thread = 2 nodes x 8 outputs (strided j).
// A = [agg/deg | x] (K=128), W = [W1l | W1r]; k-chunked (32) through smem.
// ROWSTR=36 floats (144B): keeps 16B alignment; W j-loads at worst 2-way conflict.
#define ROWSTR 36
#define NTILE  32
__global__ __launch_bounds__(256, 3) void k_layer1(const float* __restrict__ x,
                                                   const float* __restrict__ W1l,
                                                   const float* __restrict__ b1,
                                                   const float* __restrict__ W1r,
                                                   const float* __restrict__ W2l,
                                                   const float* __restrict__ W2r) {
    __shared__ __align__(16) float sA[NTILE * ROWSTR];   // 4.6 KB
    __shared__ __align__(16) float sW[128 * ROWSTR];     // 18 KB
    __shared__ float sb[HID], s2l[HID], s2r[HID], sInv[NTILE];

    int tid = threadIdx.x;
    int jgrp = tid & 15;        // output group: j = jgrp + 16*jj
    int rgrp = tid >> 4;        // node group:   node row = rgrp*2 + r
    int nb = blockIdx.x * NTILE;

    if (tid < 128) { sb[tid] = b1[tid]; s2l[tid] = W2l[tid]; s2r[tid] = W2r[tid]; }
    if (tid < NTILE) {
        int node = nb + tid;
        sInv[tid] = (node < N_NODES) ? 1.0f / fmaxf((float)g_cnt[node], 1.0f) : 0.f;
    }

    u64 acc[16];                 // [2 r][8 jj], each u64 = k-pair partial sums
#pragma unroll
    for (int q = 0; q < 16; q++) acc[q] = 0ull;

    const float4* agg4 = reinterpret_cast<const float4*>(g_agg);
    const float4* x4   = reinterpret_cast<const float4*>(x);
    const float4* wl4  = reinterpret_cast<const float4*>(W1l);
    const float4* wr4  = reinterpret_cast<const float4*>(W1r);

    for (int c = 0; c < 4; c++) {          // 4 k-chunks of 32
        __syncthreads();
        // stage A chunk: 32 rows x 8 quads = 256 (one per thread)
        {
            int row = tid >> 3, q = tid & 7;
            int node = nb + row;
            float4 av = make_float4(0.f, 0.f, 0.f, 0.f);
            if (node < N_NODES) {
                if (c < 2) {
                    av = agg4[node * 16 + c * 8 + q];
                    float iv = sInv[row];
                    av.x *= iv; av.y *= iv; av.z *= iv; av.w *= iv;
                } else {
                    av = x4[node * 16 + (c - 2) * 8 + q];
                }
            }
            *reinterpret_cast<float4*>(sA + row * ROWSTR + q * 4) = av;
        }
        // stage W chunk: 128 rows x 8 quads = 1024
        for (int idx = tid; idx < 1024; idx += 256) {
            int row = idx >> 3, q = idx & 7;
            float4 wv = (c < 2) ? wl4[row * 16 + c * 8 + q]
                                : wr4[row * 16 + (c - 2) * 8 + q];
            *reinterpret_cast<float4*>(sW + row * ROWSTR + q * 4) = wv;
        }
        __syncthreads();

#pragma unroll
        for (int kq = 0; kq < 8; kq++) {   // k-quad = 4 floats = 2 k-pairs
            u64 ar[2][2];
#pragma unroll
            for (int r = 0; r < 2; r++) {
                ulonglong2 av = *reinterpret_cast<const ulonglong2*>(
                    sA + (rgrp * 2 + r) * ROWSTR + kq * 4);
                ar[r][0] = av.x; ar[r][1] = av.y;
            }
#pragma unroll
            for (int half = 0; half < 2; half++) {
                u64 wj[4][2];
#pragma unroll
                for (int j2 = 0; j2 < 4; j2++) {
                    int j = jgrp + 16 * (half * 4 + j2);
                    ulonglong2 wv = *reinterpret_cast<const ulonglong2*>(
                        sW + j * ROWSTR + kq * 4);
                    wj[j2][0] = wv.x; wj[j2][1] = wv.y;
                }
#pragma unroll
                for (int r = 0; r < 2; r++)
#pragma unroll
                    for (int j2 = 0; j2 < 4; j2++) {
                        fma2(acc[r * 8 + half * 4 + j2], ar[r][0], wj[j2][0]);
                        fma2(acc[r * 8 + half * 4 + j2], ar[r][1], wj[j2][1]);
                    }
            }
        }
    }

    // epilogue: h = relu(dot + b); fold into rank-1 scalars; shfl-reduce over 16 jgrp lanes
#pragma unroll
    for (int r = 0; r < 2; r++) {
        float sp = 0.f, tp = 0.f;
#pragma unroll
        for (int jj = 0; jj < 8; jj++) {
            int j = jgrp + 16 * jj;
            float2 f = unpack2(acc[r * 8 + jj]);
            float h = fmaxf(f.x + f.y + sb[j], 0.f);
            sp = fmaf(h, s2l[j], sp);
            tp = fmaf(h, s2r[j], tp);
        }
#pragma unroll
        for (int m = 1; m < 16; m <<= 1) {     // all 32 lanes participate; xor stays in 16-group
            sp += __shfl_xor_sync(0xffffffffu, sp, m);
            tp += __shfl_xor_sync(0xffffffffu, tp, m);
        }
        if (jgrp == 0) {
            int node = nb + rgrp * 2 + r;
            if (node < N_NODES) { g_s[node] = sp; g_t[node] = tp; }
        }
    }
}

// ---------------- K4: layer-2 gather + v epilogue ----------------
__global__ __launch_bounds__(256) void k_gather2v(const float* __restrict__ b2l) {
    int i = blockIdx.x * blockDim.x + threadIdx.x;
    if (i >= N_NODES) return;
    int deg = g_cnt[i];
    int n = min(deg, CAP);
    const int* sl = g_slots + i * CAP;
    float acc = 0.f;
    for (int e = 0; e < n; e++) acc += g_s[sl[e]];
    float inv = 1.0f / fmaxf((float)deg, 1.0f);
    g_v[i] = fmaxf(fmaf(acc, inv, b2l[0] + g_t[i]), 0.f);
}

// ---------------- K5: z += partial(fc1_W @ v), split-K ----------------
__global__ __launch_bounds__(256) void k_fc1(const float* __restrict__ fc1W) {
    int r     = blockIdx.x & (LAST_HID - 1);
    int split = blockIdx.x >> 8;                     // 0..FC1_SPLIT-1
    const int chunk4 = (N_NODES / 4) / FC1_SPLIT;    // 3125 float4s
    int base = split * chunk4;
    const float4* wp = reinterpret_cast<const float4*>(fc1W + (size_t)r * N_NODES) + base;
    const float4* vp = reinterpret_cast<const float4*>(g_v) + base;
    float acc = 0.f;
    for (int idx = threadIdx.x; idx < chunk4; idx += 256) {
        float4 w = wp[idx];
        float4 v = vp[idx];
        acc = fmaf(w.x, v.x, acc);
        acc = fmaf(w.y, v.y, acc);
        acc = fmaf(w.z, v.z, acc);
        acc = fmaf(w.w, v.w, acc);
    }
    __shared__ float red[256];
    red[threadIdx.x] = acc;
    __syncthreads();
#pragma unroll
    for (int off = 128; off > 0; off >>= 1) {
        if (threadIdx.x < off) red[threadIdx.x] += red[threadIdx.x + off];
        __syncthreads();
    }
    if (threadIdx.x == 0) atomicAdd(&g_z[r], red[0]);
}

// ---------------- K6: pred ----------------
__global__ __launch_bounds__(256) void k_final(const float* __restrict__ fc2W,
                                               const float* __restrict__ fc2b,
                                               float* __restrict__ out) {
    __shared__ float red[256];
    int tid = threadIdx.x;
    red[tid] = fc2W[tid] * g_z[tid];
    __syncthreads();
#pragma unroll
    for (int off = 128; off > 0; off >>= 1) {
        if (tid < off) red[tid] += red[tid + off];
        __syncthreads();
    }
    if (tid == 0) out[0] = red[0] + fc2b[0];
}

// ---------------- launch ----------------
extern "C" void kernel_launch(void* const* d_in, const int* in_sizes, int n_in,
                              void* d_out, int out_size) {
    const float* x    = (const float*)d_in[0];
    const void*  ei   = d_in[1];
    const float* W1l  = (const float*)d_in[2];
    const float* b1l  = (const float*)d_in[3];
    const float* W1r  = (const float*)d_in[4];
    const float* W2l  = (const float*)d_in[5];
    const float* b2l  = (const float*)d_in[6];
    const float* W2r  = (const float*)d_in[7];
    const float* fc1W = (const float*)d_in[8];
    const float* fc1b = (const float*)d_in[9];
    const float* fc2W = (const float*)d_in[10];
    const float* fc2b = (const float*)d_in[11];
    float* out = (float*)d_out;

    k_init<<<256, 256>>>((const int*)ei, fc1b);
    k_fill<<<(N_EDGES + 255) / 256, 256>>>(ei);
    k_gather1<<<(N_NODES * 16 + 255) / 256, 256>>>(x);
    k_layer1<<<(N_NODES + NTILE - 1) / NTILE, 256>>>(x, W1l, b1l, W1r, W2l, W2r);
    k_gather2v<<<(N_NODES + 255) / 256, 256>>>(b2l);
    k_fc1<<<LAST_HID * FC1_SPLIT, 256>>>(fc1W);
    k_final<<<1, 256>>>(fc2W, fc2b, out);
}

// round 12
// speedup vs baseline: 1.1349x; 1.1261x over previous
#include <cuda_runtime.h>

#define N_NODES 50000
#define N_EDGES 800000
#define IN_CH   64
#define HID     128
#define LAST_HID 256
#define CAP     96          // per-node adjacency capacity; P(Poisson(16) > 96) ~ 1e-40
#define FC1_SPLIT 4

typedef unsigned long long u64;

// ---------------- scratch (static device arrays; no allocation) ----------------
__device__ __align__(16) float g_agg[N_NODES * IN_CH];
__device__ int   g_cnt[N_NODES];                 // degree counters (atomic cursors)
__device__ int   g_slots[N_NODES * CAP];         // bucketed adjacency: src per slot
__device__ float g_s[N_NODES];
__device__ float g_t[N_NODES];
__device__ __align__(16) float g_v[N_NODES];
__device__ float g_z[LAST_HID];
__device__ int   g_is64;

// ---------------- f32x2 helpers ----------------
__device__ __forceinline__ void fma2(u64& acc, u64 a, u64 b) {
    asm("fma.rn.f32x2 %0, %1, %2, %0;" : "+l"(acc) : "l"(a), "l"(b));
}
__device__ __forceinline__ float2 unpack2(u64 v) {
    float2 r; asm("mov.b64 {%0, %1}, %2;" : "=f"(r.x), "=f"(r.y) : "l"(v)); return r;
}

// ---------------- edge accessors ----------------
__device__ __forceinline__ int edge_at(const void* ei, int flat_idx, int is64) {
    if (is64) return (int)reinterpret_cast<const long long*>(ei)[flat_idx];
    return reinterpret_cast<const int*>(ei)[flat_idx];
}

// ---------------- K0: zero counters + seed z + detect dtype ----------------
__global__ void k_init(const int* __restrict__ ei32, const float* __restrict__ fc1b) {
    int i = blockIdx.x * blockDim.x + threadIdx.x;
    int stride = gridDim.x * blockDim.x;
    for (int j = i; j < N_NODES; j += stride) g_cnt[j] = 0;
    if (i < LAST_HID) g_z[i] = fc1b[i];
    if (i == 0) {
        int is64 = 1;
        for (int k = 0; k < 256; k++) {
            int idx = 2 * (k * 3000) + 1;      // odd int32 words, < 1.6M
            if (ei32[idx] != 0) { is64 = 0; break; }
        }
        g_is64 = is64;
    }
}

// ---------------- K1: single-pass bucket fill (adjacency + degree) ----------------
__global__ __launch_bounds__(256) void k_fill(const void* __restrict__ ei) {
    int e = blockIdx.x * blockDim.x + threadIdx.x;
    if (e >= N_EDGES) return;
    int is64 = g_is64;
    int src = edge_at(ei, e, is64);
    int dst = edge_at(ei, N_EDGES + e, is64);
    if ((unsigned)dst >= N_NODES || (unsigned)src >= N_NODES) return;
    int pos = atomicAdd(&g_cnt[dst], 1);
    if (pos < CAP) g_slots[dst * CAP + pos] = src;
}

// ---------------- K2: gather-aggregate x rows (16 threads/node, float4) ----------------
__global__ __launch_bounds__(256) void k_gather1(const float* __restrict__ x) {
    int t = blockIdx.x * blockDim.x + threadIdx.x;
    int node = t >> 4;
    if (node >= N_NODES) return;
    int lane = t & 15;
    int deg = g_cnt[node];
    int n = min(deg, CAP);
    const int* sl = g_slots + node * CAP;
    const float4* xp = reinterpret_cast<const float4*>(x);
    float4 accA = make_float4(0.f, 0.f, 0.f, 0.f);
    float4 accB = make_float4(0.f, 0.f, 0.f, 0.f);
    int e = 0;
    for (; e + 2 <= n; e += 2) {
        int s0 = sl[e];
        int s1 = sl[e + 1];
        float4 a = xp[s0 * 16 + lane];
        float4 b = xp[s1 * 16 + lane];
        accA.x += a.x; accA.y += a.y; accA.z += a.z; accA.w += a.w;
        accB.x += b.x; accB.y += b.y; accB.z += b.z; accB.w += b.w;
    }
    if (e < n) {
        int s0 = sl[e];
        float4 a = xp[s0 * 16 + lane];
        accA.x += a.x; accA.y += a.y; accA.z += a.z; accA.w += a.w;
    }
    accA.x += accB.x; accA.y += accB.y; accA.z += accB.z; accA.w += accB.w;
    reinterpret_cast<float4*>(g_agg)[node * 16 + lane] = accA;
}

// ---------------- K3: register-tiled layer1 GEMM + relu + rank-1 pre-dots ----------------
// Block tile: 64 nodes x 128 outputs; thread = 4 nodes x 8 outputs (strided j).
// A = [agg/deg | x] (K=128), W = [W1l | W1r]; k-chunked (32) through smem.
#define ROWSTR 36
#define NTILE  64
__global__ __launch_bounds__(256, 2) void k_layer1(const float* __restrict__ x,
                                                   const float* __restrict__ W1l,
                                                   const float* __restrict__ b1,
                                                   const float* __restrict__ W1r,
                                                   const float* __restrict__ W2l,
                                                   const float* __restrict__ W2r) {
    __shared__ __align__(16) float sA[NTILE * ROWSTR];   // 9.2 KB
    __shared__ __align__(16) float sW[128 * ROWSTR];     // 18 KB
    __shared__ float sb[HID], s2l[HID], s2r[HID], sInv[NTILE];

    int tid = threadIdx.x;
    int jgrp = tid & 15;        // output group: j = jgrp + 16*jj
    int rgrp = tid >> 4;        // node group (0..15): rows rgrp*4 .. rgrp*4+3
    int nb = blockIdx.x * NTILE;

    if (tid < 128) { sb[tid] = b1[tid]; s2l[tid] = W2l[tid]; s2r[tid] = W2r[tid]; }
    if (tid < NTILE) {
        int node = nb + tid;
        sInv[tid] = (node < N_NODES) ? 1.0f / fmaxf((float)g_cnt[node], 1.0f) : 0.f;
    }

    u64 acc[32];                 // [4 r][8 jj], each u64 = k-pair partial sums
#pragma unroll
    for (int q = 0; q < 32; q++) acc[q] = 0ull;

    const float4* agg4 = reinterpret_cast<const float4*>(g_agg);
    const float4* x4   = reinterpret_cast<const float4*>(x);
    const float4* wl4  = reinterpret_cast<const float4*>(W1l);
    const float4* wr4  = reinterpret_cast<const float4*>(W1r);

    for (int c = 0; c < 4; c++) {          // 4 k-chunks of 32
        __syncthreads();
        // stage A chunk: 64 rows x 8 quads = 512 (2 per thread)
        for (int idx = tid; idx < NTILE * 8; idx += 256) {
            int row = idx >> 3, q = idx & 7;
            int node = nb + row;
            float4 av = make_float4(0.f, 0.f, 0.f, 0.f);
            if (node < N_NODES) {
                if (c < 2) {
                    av = agg4[node * 16 + c * 8 + q];
                    float iv = sInv[row];
                    av.x *= iv; av.y *= iv; av.z *= iv; av.w *= iv;
                } else {
                    av = x4[node * 16 + (c - 2) * 8 + q];
                }
            }
            *reinterpret_cast<float4*>(sA + row * ROWSTR + q * 4) = av;
        }
        // stage W chunk: 128 rows x 8 quads = 1024 (4 per thread)
        for (int idx = tid; idx < 1024; idx += 256) {
            int row = idx >> 3, q = idx & 7;
            float4 wv = (c < 2) ? wl4[row * 16 + c * 8 + q]
                                : wr4[row * 16 + (c - 2) * 8 + q];
            *reinterpret_cast<float4*>(sW + row * ROWSTR + q * 4) = wv;
        }
        __syncthreads();

#pragma unroll
        for (int kq = 0; kq < 8; kq++) {   // k-quad = 4 floats = 2 k-pairs
            u64 ar[4][2];
#pragma unroll
            for (int r = 0; r < 4; r++) {
                ulonglong2 av = *reinterpret_cast<const ulonglong2*>(
                    sA + (rgrp * 4 + r) * ROWSTR + kq * 4);
                ar[r][0] = av.x; ar[r][1] = av.y;
            }
#pragma unroll
            for (int half = 0; half < 2; half++) {
                u64 wj[4][2];
#pragma unroll
                for (int j2 = 0; j2 < 4; j2++) {
                    int j = jgrp + 16 * (half * 4 + j2);
                    ulonglong2 wv = *reinterpret_cast<const ulonglong2*>(
                        sW + j * ROWSTR + kq * 4);
                    wj[j2][0] = wv.x; wj[j2][1] = wv.y;
                }
#pragma unroll
                for (int r = 0; r < 4; r++)
#pragma unroll
                    for (int j2 = 0; j2 < 4; j2++) {
                        fma2(acc[r * 8 + half * 4 + j2], ar[r][0], wj[j2][0]);
                        fma2(acc[r * 8 + half * 4 + j2], ar[r][1], wj[j2][1]);
                    }
            }
        }
    }

    // epilogue: h = relu(dot + b); fold into rank-1 scalars; shfl-reduce over 16 jgrp lanes
#pragma unroll
    for (int r = 0; r < 4; r++) {
        float sp = 0.f, tp = 0.f;
#pragma unroll
        for (int jj = 0; jj < 8; jj++) {
            int j = jgrp + 16 * jj;
            float2 f = unpack2(acc[r * 8 + jj]);
            float h = fmaxf(f.x + f.y + sb[j], 0.f);
            sp = fmaf(h, s2l[j], sp);
            tp = fmaf(h, s2r[j], tp);
        }
#pragma unroll
        for (int m = 1; m < 16; m <<= 1) {     // all 32 lanes participate; xor stays in 16-group
            sp += __shfl_xor_sync(0xffffffffu, sp, m);
            tp += __shfl_xor_sync(0xffffffffu, tp, m);
        }
        if (jgrp == 0) {
            int node = nb + rgrp * 4 + r;
            if (node < N_NODES) { g_s[node] = sp; g_t[node] = tp; }
        }
    }
}

// ---------------- K4: layer-2 gather + v epilogue ----------------
__global__ __launch_bounds__(256) void k_gather2v(const float* __restrict__ b2l) {
    int i = blockIdx.x * blockDim.x + threadIdx.x;
    if (i >= N_NODES) return;
    int deg = g_cnt[i];
    int n = min(deg, CAP);
    const int* sl = g_slots + i * CAP;
    float acc = 0.f;
    for (int e = 0; e < n; e++) acc += g_s[sl[e]];
    float inv = 1.0f / fmaxf((float)deg, 1.0f);
    g_v[i] = fmaxf(fmaf(acc, inv, b2l[0] + g_t[i]), 0.f);
}

// ---------------- K5: z += partial(fc1_W @ v), split-K ----------------
__global__ __launch_bounds__(256) void k_fc1(const float* __restrict__ fc1W) {
    int r     = blockIdx.x & (LAST_HID - 1);
    int split = blockIdx.x >> 8;                     // 0..FC1_SPLIT-1
    const int chunk4 = (N_NODES / 4) / FC1_SPLIT;    // 3125 float4s
    int base = split * chunk4;
    const float4* wp = reinterpret_cast<const float4*>(fc1W + (size_t)r * N_NODES) + base;
    const float4* vp = reinterpret_cast<const float4*>(g_v) + base;
    float acc = 0.f;
    for (int idx = threadIdx.x; idx < chunk4; idx += 256) {
        float4 w = wp[idx];
        float4 v = vp[idx];
        acc = fmaf(w.x, v.x, acc);
        acc = fmaf(w.y, v.y, acc);
        acc = fmaf(w.z, v.z, acc);
        acc = fmaf(w.w, v.w, acc);
    }
    __shared__ float red[256];
    red[threadIdx.x] = acc;
    __syncthreads();
#pragma unroll
    for (int off = 128; off > 0; off >>= 1) {
        if (threadIdx.x < off) red[threadIdx.x] += red[threadIdx.x + off];
        __syncthreads();
    }
    if (threadIdx.x == 0) atomicAdd(&g_z[r], red[0]);
}

// ---------------- K6: pred ----------------
__global__ __launch_bounds__(256) void k_final(const float* __restrict__ fc2W,
                                               const float* __restrict__ fc2b,
                                               float* __restrict__ out) {
    __shared__ float red[256];
    int tid = threadIdx.x;
    red[tid] = fc2W[tid] * g_z[tid];
    __syncthreads();
#pragma unroll
    for (int off = 128; off > 0; off >>= 1) {
        if (tid < off) red[tid] += red[tid + off];
        __syncthreads();
    }
    if (tid == 0) out[0] = red[0] + fc2b[0];
}

// ---------------- launch ----------------
extern "C" void kernel_launch(void* const* d_in, const int* in_sizes, int n_in,
                              void* d_out, int out_size) {
    const float* x    = (const float*)d_in[0];
    const void*  ei   = d_in[1];
    const float* W1l  = (const float*)d_in[2];
    const float* b1l  = (const float*)d_in[3];
    const float* W1r  = (const float*)d_in[4];
    const float* W2l  = (const float*)d_in[5];
    const float* b2l  = (const float*)d_in[6];
    const float* W2r  = (const float*)d_in[7];
    const float* fc1W = (const float*)d_in[8];
    const float* fc1b = (const float*)d_in[9];
    const float* fc2W = (const float*)d_in[10];
    const float* fc2b = (const float*)d_in[11];
    float* out = (float*)d_out;

    k_init<<<256, 256>>>((const int*)ei, fc1b);
    k_fill<<<(N_EDGES + 255) / 256, 256>>>(ei);
    k_gather1<<<(N_NODES * 16 + 255) / 256, 256>>>(x);
    k_layer1<<<(N_NODES + NTILE - 1) / NTILE, 256>>>(x, W1l, b1l, W1r, W2l, W2r);
    k_gather2v<<<(N_NODES + 255) / 256, 256>>>(b2l);
    k_fc1<<<LAST_HID * FC1_SPLIT, 256>>>(fc1W);
    k_final<<<1, 256>>>(fc2W, fc2b, out);
}